// round 3
// baseline (speedup 1.0000x reference)
#include <cuda_runtime.h>
#include <cstdint>

#define INPUT_DIM   1024
#define OUTPUT_DIM  8192
#define M_BLOCKS    8
#define TWO_PI      6.283185307179586f
#define NORM_FACT   0.03125f        /* 1/sqrt(1024), exact power of two */
#define OUT_SCALE   0.015625f       /* sqrt(2/8192) = 1/64 */

// Normalized int32 copy of the permutation table (P may arrive as int32 or int64).
__device__ int g_P32[M_BLOCKS * INPUT_DIM];

// ---------------------------------------------------------------------------
// Prep: detect int64 vs int32 layout of P and copy into g_P32.
// Deterministic, allocation-free, graph-capturable.
// ---------------------------------------------------------------------------
__global__ void prep_P_kernel(const void* __restrict__ Praw) {
    __shared__ int is64;
    if (threadIdx.x == 0) {
        // Little-endian int64 with values in [0,1024) => every odd 32-bit word
        // is zero. For int32 random data the chance all 64 probes are zero is
        // (1/1024)^64 ~ 0.
        const unsigned int* w = (const unsigned int*)Praw;
        int z = 1;
        #pragma unroll 1
        for (int i = 0; i < 64; i++) {
            if (w[2 * i + 1] != 0u) { z = 0; break; }
        }
        is64 = z;
    }
    __syncthreads();
    const int n = M_BLOCKS * INPUT_DIM;
    if (is64) {
        const long long* p = (const long long*)Praw;
        for (int j = threadIdx.x; j < n; j += blockDim.x) g_P32[j] = (int)p[j];
    } else {
        const int* p = (const int*)Praw;
        for (int j = threadIdx.x; j < n; j += blockDim.x) g_P32[j] = p[j];
    }
}

// ---------------------------------------------------------------------------
// Main kernel: one CTA per row (256 threads = 8 warps), warp m handles
// Fastfood block m. Each warp performs a full 1024-point FWHT in registers:
// 32 floats per lane; stages h=1..16 intra-thread, h=32..512 via shfl_xor
// (1 SHFL + 1 FFMA per element per stage). Only the permutation gather
// round-trips shared memory (padded layout, conflict-free stores).
// ---------------------------------------------------------------------------
__global__ void __launch_bounds__(256)
fastfood_kernel(const float* __restrict__ x,
                const float* __restrict__ B,
                const float* __restrict__ G,
                const float* __restrict__ S,
                const float* __restrict__ u_rand,
                float* __restrict__ out) {
    // Padded per-warp scratch: element j stored at j + (j>>5)  (max index 1054)
    __shared__ float seg_all[M_BLOCKS][1056];

    const int row  = blockIdx.x;
    const int m    = threadIdx.x >> 5;   // warp id = Fastfood block
    const int lane = threadIdx.x & 31;

    float* seg = seg_all[m];

    float v[32];

    // ---- load x row * B[m] : thread holds elements [32*lane, 32*lane+32) ----
    {
        const float4* xr = (const float4*)(x + (size_t)row * INPUT_DIM);
        const float4* Br = (const float4*)(B + m * INPUT_DIM);
        #pragma unroll
        for (int q = 0; q < 8; q++) {
            float4 a = xr[lane * 8 + q];
            float4 b = Br[lane * 8 + q];
            v[4 * q + 0] = a.x * b.x;
            v[4 * q + 1] = a.y * b.y;
            v[4 * q + 2] = a.z * b.z;
            v[4 * q + 3] = a.w * b.w;
        }
    }

    // ---- FWHT #1 ----
    // intra-thread stages h = 1,2,4,8,16
    #pragma unroll
    for (int h = 1; h <= 16; h <<= 1) {
        #pragma unroll
        for (int i = 0; i < 32; i++) {
            if ((i & h) == 0) {
                float a = v[i], b = v[i + h];
                v[i]     = a + b;
                v[i + h] = a - b;
            }
        }
    }
    // cross-thread stages h = 32..512 (xor distance k = h/32):
    // new = partner + sign*mine, sign = -1 on the upper half of the pair.
    #pragma unroll
    for (int k = 1; k <= 16; k <<= 1) {
        const float sign = (lane & k) ? -1.0f : 1.0f;
        #pragma unroll
        for (int i = 0; i < 32; i++) {
            float p = __shfl_xor_sync(0xffffffffu, v[i], k);
            v[i] = fmaf(sign, v[i], p);
        }
    }

    // ---- permutation gather (smem round-trip), then * G ----
    // store: element j = 32*lane + i  ->  seg[33*lane + i]  (conflict-free)
    #pragma unroll
    for (int i = 0; i < 32; i++) seg[lane * 33 + i] = v[i];
    __syncwarp();

    {
        const int4*   Pm = (const int4*)(g_P32 + m * INPUT_DIM);
        const float4* Gm = (const float4*)(G + m * INPUT_DIM);
        #pragma unroll
        for (int q = 0; q < 8; q++) {
            int4   idx = Pm[lane * 8 + q];
            float4 g   = Gm[lane * 8 + q];
            v[4 * q + 0] = seg[idx.x + (idx.x >> 5)] * g.x;
            v[4 * q + 1] = seg[idx.y + (idx.y >> 5)] * g.y;
            v[4 * q + 2] = seg[idx.z + (idx.z >> 5)] * g.z;
            v[4 * q + 3] = seg[idx.w + (idx.w >> 5)] * g.w;
        }
    }

    // ---- FWHT #2 ----
    #pragma unroll
    for (int h = 1; h <= 16; h <<= 1) {
        #pragma unroll
        for (int i = 0; i < 32; i++) {
            if ((i & h) == 0) {
                float a = v[i], b = v[i + h];
                v[i]     = a + b;
                v[i + h] = a - b;
            }
        }
    }
    #pragma unroll
    for (int k = 1; k <= 16; k <<= 1) {
        const float sign = (lane & k) ? -1.0f : 1.0f;
        #pragma unroll
        for (int i = 0; i < 32; i++) {
            float p = __shfl_xor_sync(0xffffffffu, v[i], k);
            v[i] = fmaf(sign, v[i], p);
        }
    }

    // ---- * S * norm, cos(arg + 2*pi*u) * sqrt(2/OUTPUT_DIM), store ----
    {
        const float4* Sm = (const float4*)(S + m * INPUT_DIM);
        const float4* Um = (const float4*)(u_rand + m * INPUT_DIM);
        float4* op = (float4*)(out + (size_t)row * OUTPUT_DIM + m * INPUT_DIM);
        #pragma unroll
        for (int q = 0; q < 8; q++) {
            float4 s = Sm[lane * 8 + q];
            float4 u = Um[lane * 8 + q];
            float4 r;
            r.x = __cosf(fmaf(v[4 * q + 0] * s.x, NORM_FACT, TWO_PI * u.x)) * OUT_SCALE;
            r.y = __cosf(fmaf(v[4 * q + 1] * s.y, NORM_FACT, TWO_PI * u.y)) * OUT_SCALE;
            r.z = __cosf(fmaf(v[4 * q + 2] * s.z, NORM_FACT, TWO_PI * u.z)) * OUT_SCALE;
            r.w = __cosf(fmaf(v[4 * q + 3] * s.w, NORM_FACT, TWO_PI * u.w)) * OUT_SCALE;
            op[lane * 8 + q] = r;
        }
    }
}

extern "C" void kernel_launch(void* const* d_in, const int* in_sizes, int n_in,
                              void* d_out, int out_size) {
    const float* x  = (const float*)d_in[0];
    const float* B  = (const float*)d_in[1];
    const float* G  = (const float*)d_in[2];
    const float* S  = (const float*)d_in[3];
    const void*  P  = d_in[4];             // int32 or int64, normalized by prep
    const float* u  = (const float*)d_in[5];
    float* out = (float*)d_out;

    const int rows = in_sizes[0] / INPUT_DIM;   // 8192

    prep_P_kernel<<<1, 256>>>(P);
    fastfood_kernel<<<rows, 256>>>(x, B, G, S, u, out);
}

// round 17
// speedup vs baseline: 1.5203x; 1.5203x over previous
#include <cuda_runtime.h>
#include <cstdint>

#define INPUT_DIM   1024
#define OUTPUT_DIM  8192
#define M_BLOCKS    8
#define TWO_PI      6.283185307179586f
#define NORM_FACT   0.03125f        /* 1/sqrt(1024), exact power of two */
#define OUT_SCALE   0.015625f       /* sqrt(2/8192) = 1/64 */

// Padded row stride for the 32x32 per-warp tile: 36 = 32+4 keeps float4
// stores 16B-aligned AND makes both access patterns conflict-free:
//   natural store  (addr = 36*lane + i):  banks (4*lane + i) mod 32 distinct per phase
//   transposed load (addr = 36*i + lane): banks (4*i + lane) mod 32 distinct across lanes
#define SEG_STRIDE  36
#define SEG_SIZE    (SEG_STRIDE * 32)   /* 1152 floats per warp */

// Normalized int32 copy of the permutation table (P may arrive as int32 or int64).
__device__ int g_P32[M_BLOCKS * INPUT_DIM];

// ---------------------------------------------------------------------------
// Prep: detect int64 vs int32 layout of P and copy into g_P32.
// ---------------------------------------------------------------------------
__global__ void prep_P_kernel(const void* __restrict__ Praw) {
    __shared__ int is64;
    if (threadIdx.x == 0) {
        // Little-endian int64 with values in [0,1024) => every odd 32-bit word
        // is zero. False-positive chance on int32 data: (1/1024)^64 ~ 0.
        const unsigned int* w = (const unsigned int*)Praw;
        int z = 1;
        #pragma unroll 1
        for (int i = 0; i < 64; i++) {
            if (w[2 * i + 1] != 0u) { z = 0; break; }
        }
        is64 = z;
    }
    __syncthreads();
    const int n = M_BLOCKS * INPUT_DIM;
    if (is64) {
        const long long* p = (const long long*)Praw;
        for (int j = threadIdx.x; j < n; j += blockDim.x) g_P32[j] = (int)p[j];
    } else {
        const int* p = (const int*)Praw;
        for (int j = threadIdx.x; j < n; j += blockDim.x) g_P32[j] = p[j];
    }
}

// 32-point Walsh-Hadamard transform over the register array (Sylvester order).
__device__ __forceinline__ void h32(float v[32]) {
    #pragma unroll
    for (int h = 1; h <= 16; h <<= 1) {
        #pragma unroll
        for (int i = 0; i < 32; i++) {
            if ((i & h) == 0) {
                float a = v[i], b = v[i + h];
                v[i]     = a + b;
                v[i + h] = a - b;
            }
        }
    }
}

// ---------------------------------------------------------------------------
// One CTA per row, 8 warps; warp m owns Fastfood block m.
// H_1024 = (H_32 over bits 5..9) ∘ (H_32 over bits 0..4): registers hold 32
// elements per lane, the high-bit factor is reached via one padded smem
// transpose (no shuffles anywhere).
// ---------------------------------------------------------------------------
__global__ void __launch_bounds__(256, 1)
fastfood_kernel(const float* __restrict__ x,
                const float* __restrict__ B,
                const float* __restrict__ G,
                const float* __restrict__ S,
                const float* __restrict__ u_rand,
                float* __restrict__ out) {
    __shared__ float seg_all[M_BLOCKS][SEG_SIZE];

    const int row  = blockIdx.x;
    const int m    = threadIdx.x >> 5;
    const int lane = threadIdx.x & 31;

    float* seg = seg_all[m];
    float v[32];

    // ---- load x row * B[m]: v[i] = element j = 32*lane + i (natural) ----
    {
        const float4* xr = (const float4*)(x + (size_t)row * INPUT_DIM);
        const float4* Br = (const float4*)(B + m * INPUT_DIM);
        #pragma unroll
        for (int q = 0; q < 8; q++) {
            float4 a = xr[lane * 8 + q];
            float4 b = Br[lane * 8 + q];
            v[4 * q + 0] = a.x * b.x;
            v[4 * q + 1] = a.y * b.y;
            v[4 * q + 2] = a.z * b.z;
            v[4 * q + 3] = a.w * b.w;
        }
    }

    // ================= FWHT #1 =================
    h32(v);                                  // low-bit factor (bits 0..4)
    {   // natural store (conflict-free, 16B-aligned float4)
        float4* sp = (float4*)(seg + SEG_STRIDE * lane);
        #pragma unroll
        for (int q = 0; q < 8; q++)
            sp[q] = make_float4(v[4*q+0], v[4*q+1], v[4*q+2], v[4*q+3]);
    }
    __syncwarp();
    {   // transposed load: v[i] = element 32*i + lane  (conflict-free)
        #pragma unroll
        for (int i = 0; i < 32; i++) v[i] = seg[SEG_STRIDE * i + lane];
    }
    h32(v);                                  // high-bit factor (bits 5..9)
    // v[i] = FWHT result element 32*i + lane; write back to the SAME addresses
    // each lane just read (no cross-lane hazard => no syncwarp needed before).
    #pragma unroll
    for (int i = 0; i < 32; i++) seg[SEG_STRIDE * i + lane] = v[i];
    __syncwarp();

    // ---- permutation gather, * G: back to natural layout ----
    {
        const int4*   Pm = (const int4*)(g_P32 + m * INPUT_DIM);
        const float4* Gm = (const float4*)(G + m * INPUT_DIM);
        #pragma unroll
        for (int q = 0; q < 8; q++) {
            int4   idx = Pm[lane * 8 + q];
            float4 g   = Gm[lane * 8 + q];
            v[4*q+0] = seg[SEG_STRIDE * (idx.x >> 5) + (idx.x & 31)] * g.x;
            v[4*q+1] = seg[SEG_STRIDE * (idx.y >> 5) + (idx.y & 31)] * g.y;
            v[4*q+2] = seg[SEG_STRIDE * (idx.z >> 5) + (idx.z & 31)] * g.z;
            v[4*q+3] = seg[SEG_STRIDE * (idx.w >> 5) + (idx.w & 31)] * g.w;
        }
    }

    // ================= FWHT #2 =================
    h32(v);                                  // low-bit factor
    __syncwarp();                            // WAR: gather reads vs stores below
    {
        float4* sp = (float4*)(seg + SEG_STRIDE * lane);
        #pragma unroll
        for (int q = 0; q < 8; q++)
            sp[q] = make_float4(v[4*q+0], v[4*q+1], v[4*q+2], v[4*q+3]);
    }
    __syncwarp();
    {
        #pragma unroll
        for (int i = 0; i < 32; i++) v[i] = seg[SEG_STRIDE * i + lane];
    }
    h32(v);                                  // high-bit factor
    // v[i] = output element e = 32*i + lane (transposed layout)

    // ---- epilogue: * S * norm, cos(arg + 2*pi*u) * OUT_SCALE, store ----
    {
        const float* Sm = S      + m * INPUT_DIM;
        const float* Um = u_rand + m * INPUT_DIM;
        float* op = out + (size_t)row * OUTPUT_DIM + m * INPUT_DIM;
        #pragma unroll
        for (int i = 0; i < 32; i++) {
            const int e = 32 * i + lane;     // coalesced across lanes
            float arg = fmaf(v[i] * Sm[e], NORM_FACT, TWO_PI * Um[e]);
            op[e] = __cosf(arg) * OUT_SCALE;
        }
    }
}

extern "C" void kernel_launch(void* const* d_in, const int* in_sizes, int n_in,
                              void* d_out, int out_size) {
    const float* x  = (const float*)d_in[0];
    const float* B  = (const float*)d_in[1];
    const float* G  = (const float*)d_in[2];
    const float* S  = (const float*)d_in[3];
    const void*  P  = d_in[4];             // int32 or int64, normalized by prep
    const float* u  = (const float*)d_in[5];
    float* out = (float*)d_out;

    const int rows = in_sizes[0] / INPUT_DIM;   // 8192

    prep_P_kernel<<<1, 256>>>(P);
    fastfood_kernel<<<rows, 256>>>(x, B, G, S, u, out);
}